// round 6
// baseline (speedup 1.0000x reference)
#include <cuda_runtime.h>
#include <cuda_bf16.h>
#include <cstdint>

#define N_BATCH 1024
#define T_STEPS 64
#define D_IN    512
#define H_DIM   1024
#define G4      4096
#define K2      2048
typedef __nv_bfloat16 bf16;

__device__ float g_XW [(size_t)N_BATCH * T_STEPS * G4];
__device__ bf16  g_xh [(size_t)N_BATCH * T_STEPS * D_IN];
__device__ bf16  g_xl [(size_t)N_BATCH * T_STEPS * D_IN];
__device__ bf16  g_Wxh[(size_t)G4 * D_IN];
__device__ bf16  g_Wxl[(size_t)G4 * D_IN];
__device__ bf16  g_Wch[(size_t)G4 * K2];
__device__ bf16  g_Wcl[(size_t)G4 * K2];
__device__ bf16  g_A2h[(size_t)N_BATCH * K2];
__device__ bf16  g_A2l[(size_t)N_BATCH * K2];
__device__ float g_c [(size_t)N_BATCH * H_DIM];
__device__ float g_hw[(size_t)N_BATCH * G4];

// ---- helpers ----
__device__ __forceinline__ uint32_t s2u(const void* p) {
    uint32_t a;
    asm("{.reg .u64 t; cvta.to.shared.u64 t, %1; cvt.u32.u64 %0, t;}" : "=r"(a) : "l"(p));
    return a;
}
#define SW128(o) ((o) ^ (((o) >> 3) & 0x70))
__device__ __forceinline__ void cpa(uint32_t s, const void* g) {
    asm volatile("cp.async.cg.shared.global [%0], [%1], 16;" :: "r"(s), "l"(g));
}
#define CP_COMMIT() asm volatile("cp.async.commit_group;" ::: "memory")
#define CP_WAIT1()  asm volatile("cp.async.wait_group 1;" ::: "memory")

__device__ __forceinline__ void mma16816(float* c, const uint32_t* a, const uint32_t* b) {
    asm volatile("mma.sync.aligned.m16n8k16.row.col.f32.bf16.bf16.f32 "
        "{%0,%1,%2,%3}, {%4,%5,%6,%7}, {%8,%9}, {%0,%1,%2,%3};"
        : "+f"(c[0]), "+f"(c[1]), "+f"(c[2]), "+f"(c[3])
        : "r"(a[0]), "r"(a[1]), "r"(a[2]), "r"(a[3]), "r"(b[0]), "r"(b[1]));
}
__device__ __forceinline__ void ldsm4(uint32_t* r, uint32_t a) {
    asm volatile("ldmatrix.sync.aligned.m8n8.x4.shared.b16 {%0,%1,%2,%3}, [%4];"
        : "=r"(r[0]), "=r"(r[1]), "=r"(r[2]), "=r"(r[3]) : "r"(a));
}
__device__ __forceinline__ void ldsm2(uint32_t* r, uint32_t a) {
    asm volatile("ldmatrix.sync.aligned.m8n8.x2.shared.b16 {%0,%1}, [%2];"
        : "=r"(r[0]), "=r"(r[1]) : "r"(a));
}
__device__ __forceinline__ void bsplit(float x, bf16& hi, bf16& lo) {
    hi = __float2bfloat16(x);
    lo = __float2bfloat16(x - __bfloat162float(hi));
}

// ===== GEMM: C[M,Nc] = splitA[M,K](lda) @ splitB[Nc,K](ldb)^T (+bias) ========
// 128x128 tile, BK=32, hi|lo interleaved in 128B rows, 3-stage cp.async,
// 8 warps (2Mx4N), 2 CTAs/SM. Stage: A 16KB | B 16KB = 32KB. smem 96KB.
#define GSMEM (3 * 32768)
template <bool BIAS>
__global__ void __launch_bounds__(256, 2)
gemm_kernel(const bf16* __restrict__ Ah, const bf16* __restrict__ Al, int lda,
            const bf16* __restrict__ Bh, const bf16* __restrict__ Bl, int ldb,
            const float* __restrict__ bias, float* __restrict__ C, int K, int Nc) {
    extern __shared__ char smx[];
    const uint32_t sb = s2u(smx);
    const int tid = threadIdx.x, wid = tid >> 5, lane = tid & 31;
    const int bm = blockIdx.y * 128, bn = blockIdx.x * 128;
    const int wm = (wid >> 2) * 64, wn = (wid & 3) * 32;

    // loader: chunk u = tid + i*256; row = u>>3; 16B slot = (u&7)
    //   slots 0-3: hi half (k bytes [0,64)), slots 4-7: lo half ([64,128))
    uint32_t so[4];
#pragma unroll
    for (int i = 0; i < 4; i++) {
        int u = tid + i * 256;
        so[i] = SW128((uint32_t)((u >> 3) * 128 + (u & 7) * 16));
    }

    const int KT = K / 32;
    float acc[4][4][4];
#pragma unroll
    for (int mt = 0; mt < 4; mt++)
#pragma unroll
        for (int nt = 0; nt < 4; nt++)
#pragma unroll
            for (int v = 0; v < 4; v++) acc[mt][nt][v] = 0.f;

    auto load_stage = [&](int kt, int st) {
        if (kt < KT) {
            uint32_t s0 = sb + st * 32768;
#pragma unroll
            for (int i = 0; i < 4; i++) {
                int u = tid + i * 256;
                int row = u >> 3;
                int half = (u >> 2) & 1;
                int kc = (u & 3) * 8;
                size_t ga = (size_t)(bm + row) * lda + kt * 32 + kc;
                size_t gb = (size_t)(bn + row) * ldb + kt * 32 + kc;
                cpa(s0 + so[i],         (half ? Al : Ah) + ga);
                cpa(s0 + 16384 + so[i], (half ? Bl : Bh) + gb);
            }
        }
        CP_COMMIT();
    };

    load_stage(0, 0);
    load_stage(1, 1);

    const int arow  = wm + (lane & 7) + ((lane >> 3) & 1) * 8;
    const int acolb = ((lane >> 4) & 1) * 16;
    const int brow  = wn + (lane & 7);
    const int bcolb = ((lane >> 3) & 1) * 16;

    for (int kt = 0; kt < KT; kt++) {
        CP_WAIT1();
        __syncthreads();
        load_stage(kt + 2, (kt + 2) % 3);

        uint32_t s0 = sb + (kt % 3) * 32768;
#pragma unroll
        for (int ks = 0; ks < 2; ks++) {
            uint32_t ah[4][4], al[4][4], bh[4][2], bl[4][2];
#pragma unroll
            for (int mt = 0; mt < 4; mt++) {
                int rb = (arow + mt * 16) * 128 + ks * 32 + acolb;
                ldsm4(ah[mt], s0 + SW128((uint32_t)rb));
                ldsm4(al[mt], s0 + SW128((uint32_t)(rb + 64)));
            }
#pragma unroll
            for (int nt = 0; nt < 4; nt++) {
                int rb = (brow + nt * 8) * 128 + ks * 32 + bcolb;
                ldsm2(bh[nt], s0 + 16384 + SW128((uint32_t)rb));
                ldsm2(bl[nt], s0 + 16384 + SW128((uint32_t)(rb + 64)));
            }
#pragma unroll
            for (int mt = 0; mt < 4; mt++)
#pragma unroll
                for (int nt = 0; nt < 4; nt++) {
                    mma16816(acc[mt][nt], ah[mt], bh[nt]);
                    mma16816(acc[mt][nt], ah[mt], bl[nt]);
                    mma16816(acc[mt][nt], al[mt], bh[nt]);
                }
        }
        __syncthreads();
    }

    const int q = lane >> 2, i2 = (lane & 3) * 2;
#pragma unroll
    for (int mt = 0; mt < 4; mt++) {
        int row0 = bm + wm + mt * 16 + q;
#pragma unroll
        for (int nt = 0; nt < 4; nt++) {
            int col = bn + wn + nt * 8 + i2;
            float2 v0 = make_float2(acc[mt][nt][0], acc[mt][nt][1]);
            float2 v1 = make_float2(acc[mt][nt][2], acc[mt][nt][3]);
            if (BIAS) {
                float2 bb = *(const float2*)(bias + col);
                v0.x += bb.x; v0.y += bb.y; v1.x += bb.x; v1.y += bb.y;
            }
            *(float2*)(C + (size_t)row0 * Nc + col)       = v0;
            *(float2*)(C + (size_t)(row0 + 8) * Nc + col) = v1;
        }
    }
}

// ---- shared attention body: h in smem -> scores -> softmax -> attn splits ---
__device__ __forceinline__ void attn_body(const float* __restrict__ Af,
                                          const float* h_sh, float* red, float* w_sh,
                                          bf16* A2h, bf16* A2l, int n, int tid) {
    float part[16];
#pragma unroll
    for (int l = 0; l < 16; l++) part[l] = 0.f;
    const float* Ab = Af + (size_t)n * (H_DIM * 16);
    float4 rows[4][4];
#pragma unroll
    for (int k = 0; k < 4; k++) {
        int hh = tid + k * 256;
        float hv = h_sh[hh];
        const float4* row = (const float4*)(Ab + (size_t)hh * 16);
#pragma unroll
        for (int q = 0; q < 4; q++) rows[k][q] = row[q];
#pragma unroll
        for (int q = 0; q < 4; q++) {
            part[4 * q + 0] += hv * rows[k][q].x;
            part[4 * q + 1] += hv * rows[k][q].y;
            part[4 * q + 2] += hv * rows[k][q].z;
            part[4 * q + 3] += hv * rows[k][q].w;
        }
    }
#pragma unroll
    for (int l = 0; l < 16; l++) {
        float v = part[l];
        v += __shfl_down_sync(~0u, v, 16);
        v += __shfl_down_sync(~0u, v, 8);
        v += __shfl_down_sync(~0u, v, 4);
        v += __shfl_down_sync(~0u, v, 2);
        v += __shfl_down_sync(~0u, v, 1);
        if ((tid & 31) == 0) atomicAdd(&red[l], v);
    }
    __syncthreads();
    if (tid == 0) {
        float s[16], mx = -1e30f, sum = 0.f;
#pragma unroll
        for (int l = 0; l < 16; l++) { s[l] = red[l] * 0.03125f; mx = fmaxf(mx, s[l]); }
#pragma unroll
        for (int l = 0; l < 16; l++) { s[l] = expf(s[l] - mx); sum += s[l]; }
        float inv = 1.f / sum;
#pragma unroll
        for (int l = 0; l < 16; l++) w_sh[l] = s[l] * inv;
    }
    __syncthreads();
    float w[16];
#pragma unroll
    for (int l = 0; l < 16; l++) w[l] = w_sh[l];
#pragma unroll
    for (int k = 0; k < 4; k++) {
        int hh = tid + k * 256;
        float acc = 0.f;
#pragma unroll
        for (int q = 0; q < 4; q++) {
            acc += w[4 * q + 0] * rows[k][q].x + w[4 * q + 1] * rows[k][q].y
                 + w[4 * q + 2] * rows[k][q].z + w[4 * q + 3] * rows[k][q].w;
        }
        bf16 hi, lo; bsplit(acc, hi, lo);
        A2h[(size_t)n * K2 + H_DIM + hh] = hi;
        A2l[(size_t)n * K2 + H_DIM + hh] = lo;
    }
}

// ---- prep (block per n): h0=c0=mean(Af), h splits, then inline attention ----
__global__ void prep_kernel(const float* __restrict__ Af, float* c0,
                            bf16* A2h, bf16* A2l) {
    __shared__ float h_sh[H_DIM];
    __shared__ float red[16];
    __shared__ float w_sh[16];
    const int n = blockIdx.x, tid = threadIdx.x;
    if (tid < 16) red[tid] = 0.f;
#pragma unroll
    for (int k = 0; k < 4; k++) {
        int hh = tid + k * 256;
        const float4* src = (const float4*)(Af + ((size_t)n * H_DIM + hh) * 16);
        float s = 0.f;
#pragma unroll
        for (int q = 0; q < 4; q++) { float4 r = src[q]; s += r.x + r.y + r.z + r.w; }
        float m = s * 0.0625f;
        c0[(size_t)n * H_DIM + hh] = m;
        h_sh[hh] = m;
        bf16 hi, lo; bsplit(m, hi, lo);
        A2h[(size_t)n * K2 + hh] = hi; A2l[(size_t)n * K2 + hh] = lo;
    }
    __syncthreads();
    attn_body(Af, h_sh, red, w_sh, A2h, A2l, n, tid);
}

__global__ void splitx_kernel(const float* __restrict__ x, bf16* xh, bf16* xl) {
    int i = blockIdx.x * blockDim.x + threadIdx.x;
    bf16 hi, lo; bsplit(x[i], hi, lo);
    xh[i] = hi; xl[i] = lo;
}
__global__ void twx_kernel(const float* __restrict__ Wx, bf16* th, bf16* tl) {
    int i = blockIdx.x * blockDim.x + threadIdx.x;   // n*512 + k
    int n = i >> 9, k = i & 511;
    bf16 hi, lo; bsplit(Wx[(size_t)k * G4 + n], hi, lo);
    th[i] = hi; tl[i] = lo;
}
__global__ void twc_kernel(const float* __restrict__ Wh, const float* __restrict__ Wa,
                           bf16* th, bf16* tl) {
    int i = blockIdx.x * blockDim.x + threadIdx.x;   // n*2048 + k
    int n = i >> 11, k = i & 2047;
    float v = (k < H_DIM) ? Wh[(size_t)k * G4 + n] : Wa[(size_t)(k - H_DIM) * G4 + n];
    bf16 hi, lo; bsplit(v, hi, lo);
    th[i] = hi; tl[i] = lo;
}

// ---- fused LSTM gates + attention (block per n) ------------------------------
__global__ void lstm_attn_kernel(const float* __restrict__ hw, const float* __restrict__ XW,
                                 const float* __restrict__ Af,
                                 float* __restrict__ c,
                                 bf16* A2h, bf16* A2l, float* __restrict__ out, int t) {
    __shared__ float h_sh[H_DIM];
    __shared__ float red[16];
    __shared__ float w_sh[16];
    const int n = blockIdx.x, tid = threadIdx.x;
    if (tid < 16) red[tid] = 0.f;
    const float* hr = hw + (size_t)n * G4;
    const float* xr = XW + ((size_t)n * T_STEPS + t) * G4;
#pragma unroll
    for (int k = 0; k < 4; k++) {
        int j = tid + k * 256;
        size_t idx = (size_t)n * H_DIM + j;
        float ai = hr[j] + xr[j];
        float af = hr[H_DIM + j] + xr[H_DIM + j];
        float ao = hr[2 * H_DIM + j] + xr[2 * H_DIM + j];
        float ag = hr[3 * H_DIM + j] + xr[3 * H_DIM + j];
        float i_ = 1.f / (1.f + expf(-ai));
        float f_ = 1.f / (1.f + expf(-af));
        float o_ = 1.f / (1.f + expf(-ao));
        float g_ = tanhf(ag);
        float cn = f_ * c[idx] + i_ * g_;
        float hn = o_ * tanhf(cn);
        c[idx] = cn;
        h_sh[j] = hn;
        out[((size_t)n * T_STEPS + t) * H_DIM + j] = hn;
        bf16 hi, lo; bsplit(hn, hi, lo);
        A2h[(size_t)n * K2 + j] = hi;
        A2l[(size_t)n * K2 + j] = lo;
    }
    __syncthreads();
    attn_body(Af, h_sh, red, w_sh, A2h, A2l, n, tid);
}

extern "C" void kernel_launch(void* const* d_in, const int* in_sizes, int n_in,
                              void* d_out, int out_size) {
    const float* x     = (const float*)d_in[0];
    const float* Af    = (const float*)d_in[1];
    const float* Wx    = (const float*)d_in[2];
    const float* Wh    = (const float*)d_in[3];
    const float* Wattn = (const float*)d_in[4];
    const float* b     = (const float*)d_in[5];
    float* out = (float*)d_out;

    float *XW, *c, *hw;
    bf16 *xh, *xl, *Wxh, *Wxl, *Wch, *Wcl, *A2h, *A2l;
    cudaGetSymbolAddress((void**)&XW, g_XW);
    cudaGetSymbolAddress((void**)&xh, g_xh);   cudaGetSymbolAddress((void**)&xl, g_xl);
    cudaGetSymbolAddress((void**)&Wxh, g_Wxh); cudaGetSymbolAddress((void**)&Wxl, g_Wxl);
    cudaGetSymbolAddress((void**)&Wch, g_Wch); cudaGetSymbolAddress((void**)&Wcl, g_Wcl);
    cudaGetSymbolAddress((void**)&A2h, g_A2h); cudaGetSymbolAddress((void**)&A2l, g_A2l);
    cudaGetSymbolAddress((void**)&c, g_c);     cudaGetSymbolAddress((void**)&hw, g_hw);

    cudaFuncSetAttribute(gemm_kernel<true>,  cudaFuncAttributeMaxDynamicSharedMemorySize, GSMEM);
    cudaFuncSetAttribute(gemm_kernel<false>, cudaFuncAttributeMaxDynamicSharedMemorySize, GSMEM);

    prep_kernel<<<N_BATCH, 256>>>(Af, c, A2h, A2l);
    splitx_kernel<<<(N_BATCH * T_STEPS * D_IN) / 256, 256>>>(x, xh, xl);
    twx_kernel<<<(G4 * D_IN) / 256, 256>>>(Wx, Wxh, Wxl);
    twc_kernel<<<(G4 * K2) / 256, 256>>>(Wh, Wattn, Wch, Wcl);

    // XW = x @ Wx + b for all t  (M = N*T = 65536)
    {
        dim3 grid(G4 / 128, (N_BATCH * T_STEPS) / 128);
        gemm_kernel<true><<<grid, 256, GSMEM>>>(xh, xl, D_IN, Wxh, Wxl, D_IN, b, XW, D_IN, G4);
    }

    dim3 gstep(G4 / 128, N_BATCH / 128);
    for (int t = 0; t < T_STEPS; t++) {
        gemm_kernel<false><<<gstep, 256, GSMEM>>>(A2h, A2l, K2, Wch, Wcl, K2, nullptr, hw, K2, G4);
        lstm_attn_kernel<<<N_BATCH, 256>>>(hw, XW, Af, c, A2h, A2l, out, t);
    }
}

// round 7
// speedup vs baseline: 1.1283x; 1.1283x over previous
#include <cuda_runtime.h>
#include <cuda_bf16.h>
#include <cstdint>

#define N_BATCH 1024
#define T_STEPS 64
#define D_IN    512
#define H_DIM   1024
#define G4      4096
#define K2      2048
typedef __nv_bfloat16 bf16;

__device__ float g_XW [(size_t)N_BATCH * T_STEPS * G4];
__device__ bf16  g_xh [(size_t)N_BATCH * T_STEPS * D_IN];
__device__ bf16  g_xl [(size_t)N_BATCH * T_STEPS * D_IN];
__device__ bf16  g_Wxh[(size_t)G4 * D_IN];
__device__ bf16  g_Wxl[(size_t)G4 * D_IN];
__device__ bf16  g_Wch[(size_t)G4 * K2];
__device__ bf16  g_Wcl[(size_t)G4 * K2];
__device__ bf16  g_A2h[(size_t)N_BATCH * K2];
__device__ bf16  g_A2l[(size_t)N_BATCH * K2];
__device__ float g_c [(size_t)N_BATCH * H_DIM];
__device__ float g_hw[(size_t)N_BATCH * G4];

// ---- helpers ----
__device__ __forceinline__ uint32_t s2u(const void* p) {
    uint32_t a;
    asm("{.reg .u64 t; cvta.to.shared.u64 t, %1; cvt.u32.u64 %0, t;}" : "=r"(a) : "l"(p));
    return a;
}
#define SW128(o) ((o) ^ (((o) >> 3) & 0x70))
__device__ __forceinline__ void cpa(uint32_t s, const void* g) {
    asm volatile("cp.async.cg.shared.global [%0], [%1], 16;" :: "r"(s), "l"(g));
}
#define CP_COMMIT() asm volatile("cp.async.commit_group;" ::: "memory")
#define CP_WAIT1()  asm volatile("cp.async.wait_group 1;" ::: "memory")

__device__ __forceinline__ void mma16816(float* c, const uint32_t* a, const uint32_t* b) {
    asm volatile("mma.sync.aligned.m16n8k16.row.col.f32.bf16.bf16.f32 "
        "{%0,%1,%2,%3}, {%4,%5,%6,%7}, {%8,%9}, {%0,%1,%2,%3};"
        : "+f"(c[0]), "+f"(c[1]), "+f"(c[2]), "+f"(c[3])
        : "r"(a[0]), "r"(a[1]), "r"(a[2]), "r"(a[3]), "r"(b[0]), "r"(b[1]));
}
__device__ __forceinline__ void ldsm4(uint32_t* r, uint32_t a) {
    asm volatile("ldmatrix.sync.aligned.m8n8.x4.shared.b16 {%0,%1,%2,%3}, [%4];"
        : "=r"(r[0]), "=r"(r[1]), "=r"(r[2]), "=r"(r[3]) : "r"(a));
}
__device__ __forceinline__ void ldsm2(uint32_t* r, uint32_t a) {
    asm volatile("ldmatrix.sync.aligned.m8n8.x2.shared.b16 {%0,%1}, [%2];"
        : "=r"(r[0]), "=r"(r[1]) : "r"(a));
}
__device__ __forceinline__ void bsplit(float x, bf16& hi, bf16& lo) {
    hi = __float2bfloat16(x);
    lo = __float2bfloat16(x - __bfloat162float(hi));
}

// ===== XW GEMM (R5-proven): 128x128, BK=64, 3-stage, 256 thr, 192KB =========
#define GSMEM (3 * 65536)
__global__ void __launch_bounds__(256, 1)
gemm_kernel(const bf16* __restrict__ Ah, const bf16* __restrict__ Al, int lda,
            const bf16* __restrict__ Bh, const bf16* __restrict__ Bl, int ldb,
            const float* __restrict__ bias, float* __restrict__ C, int K, int Nc) {
    extern __shared__ char smx[];
    const uint32_t sb = s2u(smx);
    const int tid = threadIdx.x, wid = tid >> 5, lane = tid & 31;
    const int bm = blockIdx.y * 128, bn = blockIdx.x * 128;
    const int wm = (wid >> 2) * 64, wn = (wid & 3) * 32;

    uint32_t so[4];
#pragma unroll
    for (int i = 0; i < 4; i++)
        so[i] = SW128((uint32_t)(((tid >> 3) + i * 32) * 128 + (tid & 7) * 16));

    const int KT = K / 64;
    float acc[4][4][4];
#pragma unroll
    for (int mt = 0; mt < 4; mt++)
#pragma unroll
        for (int nt = 0; nt < 4; nt++)
#pragma unroll
            for (int v = 0; v < 4; v++) acc[mt][nt][v] = 0.f;

    auto load_stage = [&](int kt, int st) {
        if (kt < KT) {
            uint32_t s0 = sb + st * 65536;
#pragma unroll
            for (int i = 0; i < 4; i++) {
                int r = (tid >> 3) + i * 32;
                size_t ga = (size_t)(bm + r) * lda + kt * 64 + (tid & 7) * 8;
                size_t gb = (size_t)(bn + r) * ldb + kt * 64 + (tid & 7) * 8;
                cpa(s0 + so[i],         Ah + ga);
                cpa(s0 + 16384 + so[i], Al + ga);
                cpa(s0 + 32768 + so[i], Bh + gb);
                cpa(s0 + 49152 + so[i], Bl + gb);
            }
        }
        CP_COMMIT();
    };

    load_stage(0, 0);
    load_stage(1, 1);

    const int arow  = wm + (lane & 7) + ((lane >> 3) & 1) * 8;
    const int acolb = ((lane >> 4) & 1) * 16;
    const int brow  = wn + (lane & 7);
    const int bcolb = ((lane >> 3) & 1) * 16;

    for (int kt = 0; kt < KT; kt++) {
        CP_WAIT1();
        __syncthreads();
        load_stage(kt + 2, (kt + 2) % 3);

        uint32_t s0 = sb + (kt % 3) * 65536;
#pragma unroll
        for (int ks = 0; ks < 4; ks++) {
            uint32_t ah[4][4], al[4][4], bh[4][2], bl[4][2];
#pragma unroll
            for (int mt = 0; mt < 4; mt++) {
                uint32_t off = SW128((uint32_t)((arow + mt * 16) * 128 + ks * 32 + acolb));
                ldsm4(ah[mt], s0 + off);
                ldsm4(al[mt], s0 + 16384 + off);
            }
#pragma unroll
            for (int nt = 0; nt < 4; nt++) {
                uint32_t off = SW128((uint32_t)((brow + nt * 8) * 128 + ks * 32 + bcolb));
                ldsm2(bh[nt], s0 + 32768 + off);
                ldsm2(bl[nt], s0 + 49152 + off);
            }
#pragma unroll
            for (int mt = 0; mt < 4; mt++)
#pragma unroll
                for (int nt = 0; nt < 4; nt++) {
                    mma16816(acc[mt][nt], ah[mt], bh[nt]);
                    mma16816(acc[mt][nt], ah[mt], bl[nt]);
                    mma16816(acc[mt][nt], al[mt], bh[nt]);
                }
        }
        __syncthreads();
    }

    const int q = lane >> 2, i2 = (lane & 3) * 2;
#pragma unroll
    for (int mt = 0; mt < 4; mt++) {
        int row0 = bm + wm + mt * 16 + q;
#pragma unroll
        for (int nt = 0; nt < 4; nt++) {
            int col = bn + wn + nt * 8 + i2;
            float2 v0 = make_float2(acc[mt][nt][0], acc[mt][nt][1]);
            float2 v1 = make_float2(acc[mt][nt][2], acc[mt][nt][3]);
            float2 bb = *(const float2*)(bias + col);
            v0.x += bb.x; v0.y += bb.y; v1.x += bb.x; v1.y += bb.y;
            *(float2*)(C + (size_t)row0 * Nc + col)       = v0;
            *(float2*)(C + (size_t)(row0 + 8) * Nc + col) = v1;
        }
    }
}

// ===== STEP GEMM: one-wave 128x256 tile, 512 thr (2Mx8N warps), BK=64, ======
// 2-stage. Stage: Ah16K|Al16K|Bh32K|Bl32K = 96KB; smem 192KB. grid 16x8=128.
#define GSMEM2 (2 * 98304)
__global__ void __launch_bounds__(512, 1)
gemm_step_kernel(const bf16* __restrict__ Ah, const bf16* __restrict__ Al,
                 const bf16* __restrict__ Bh, const bf16* __restrict__ Bl,
                 float* __restrict__ C) {
    extern __shared__ char smx[];
    const uint32_t sb = s2u(smx);
    const int tid = threadIdx.x, wid = tid >> 5, lane = tid & 31;
    const int bm = blockIdx.y * 128, bn = blockIdx.x * 256;
    const int wm = (wid >> 3) * 64, wn = (wid & 7) * 32;
    const int KT = K2 / 64;   // 32

    uint32_t soA[2], soB[4];
#pragma unroll
    for (int i = 0; i < 2; i++) {
        int u = tid + i * 512;
        soA[i] = SW128((uint32_t)((u >> 3) * 128 + (u & 7) * 16));
    }
#pragma unroll
    for (int i = 0; i < 4; i++) {
        int u = tid + i * 512;
        soB[i] = SW128((uint32_t)((u >> 3) * 128 + (u & 7) * 16));
    }

    float acc[4][4][4];
#pragma unroll
    for (int mt = 0; mt < 4; mt++)
#pragma unroll
        for (int nt = 0; nt < 4; nt++)
#pragma unroll
            for (int v = 0; v < 4; v++) acc[mt][nt][v] = 0.f;

    auto load_stage = [&](int kt, int st) {
        if (kt < KT) {
            uint32_t s0 = sb + st * 98304;
#pragma unroll
            for (int i = 0; i < 2; i++) {
                int u = tid + i * 512;
                size_t ga = (size_t)(bm + (u >> 3)) * K2 + kt * 64 + (u & 7) * 8;
                cpa(s0 + soA[i],         Ah + ga);
                cpa(s0 + 16384 + soA[i], Al + ga);
            }
#pragma unroll
            for (int i = 0; i < 4; i++) {
                int u = tid + i * 512;
                size_t gb = (size_t)(bn + (u >> 3)) * K2 + kt * 64 + (u & 7) * 8;
                cpa(s0 + 32768 + soB[i], Bh + gb);
                cpa(s0 + 65536 + soB[i], Bl + gb);
            }
        }
        CP_COMMIT();
    };

    load_stage(0, 0);
    load_stage(1, 1);

    const int arow  = wm + (lane & 7) + ((lane >> 3) & 1) * 8;
    const int acolb = ((lane >> 4) & 1) * 16;
    const int brow  = wn + (lane & 7);
    const int bcolb = ((lane >> 3) & 1) * 16;

    for (int kt = 0; kt < KT; kt++) {
        CP_WAIT1();
        __syncthreads();
        uint32_t s0 = sb + (kt & 1) * 98304;
#pragma unroll
        for (int ks = 0; ks < 4; ks++) {
            uint32_t ah[4][4], al[4][4], bh[4][2], bl[4][2];
#pragma unroll
            for (int mt = 0; mt < 4; mt++) {
                uint32_t off = SW128((uint32_t)((arow + mt * 16) * 128 + ks * 32 + acolb));
                ldsm4(ah[mt], s0 + off);
                ldsm4(al[mt], s0 + 16384 + off);
            }
#pragma unroll
            for (int nt = 0; nt < 4; nt++) {
                uint32_t off = SW128((uint32_t)((brow + nt * 8) * 128 + ks * 32 + bcolb));
                ldsm2(bh[nt], s0 + 32768 + off);
                ldsm2(bl[nt], s0 + 65536 + off);
            }
#pragma unroll
            for (int mt = 0; mt < 4; mt++)
#pragma unroll
                for (int nt = 0; nt < 4; nt++) {
                    mma16816(acc[mt][nt], ah[mt], bh[nt]);
                    mma16816(acc[mt][nt], ah[mt], bl[nt]);
                    mma16816(acc[mt][nt], al[mt], bh[nt]);
                }
        }
        __syncthreads();
        load_stage(kt + 2, kt & 1);
    }

    const int q = lane >> 2, i2 = (lane & 3) * 2;
#pragma unroll
    for (int mt = 0; mt < 4; mt++) {
        int row0 = bm + wm + mt * 16 + q;
#pragma unroll
        for (int nt = 0; nt < 4; nt++) {
            int col = bn + wn + nt * 8 + i2;
            *(float2*)(C + (size_t)row0 * G4 + col) =
                make_float2(acc[mt][nt][0], acc[mt][nt][1]);
            *(float2*)(C + (size_t)(row0 + 8) * G4 + col) =
                make_float2(acc[mt][nt][2], acc[mt][nt][3]);
        }
    }
}

// ---- shared attention body -----------------------------------------------
__device__ __forceinline__ void attn_body(const float* __restrict__ Af,
                                          const float* h_sh, float* red, float* w_sh,
                                          bf16* A2h, bf16* A2l, int n, int tid) {
    float part[16];
#pragma unroll
    for (int l = 0; l < 16; l++) part[l] = 0.f;
    const float* Ab = Af + (size_t)n * (H_DIM * 16);
    float4 rows[4][4];
#pragma unroll
    for (int k = 0; k < 4; k++) {
        int hh = tid + k * 256;
        float hv = h_sh[hh];
        const float4* row = (const float4*)(Ab + (size_t)hh * 16);
#pragma unroll
        for (int q = 0; q < 4; q++) rows[k][q] = row[q];
#pragma unroll
        for (int q = 0; q < 4; q++) {
            part[4 * q + 0] += hv * rows[k][q].x;
            part[4 * q + 1] += hv * rows[k][q].y;
            part[4 * q + 2] += hv * rows[k][q].z;
            part[4 * q + 3] += hv * rows[k][q].w;
        }
    }
#pragma unroll
    for (int l = 0; l < 16; l++) {
        float v = part[l];
        v += __shfl_down_sync(~0u, v, 16);
        v += __shfl_down_sync(~0u, v, 8);
        v += __shfl_down_sync(~0u, v, 4);
        v += __shfl_down_sync(~0u, v, 2);
        v += __shfl_down_sync(~0u, v, 1);
        if ((tid & 31) == 0) atomicAdd(&red[l], v);
    }
    __syncthreads();
    if (tid == 0) {
        float s[16], mx = -1e30f, sum = 0.f;
#pragma unroll
        for (int l = 0; l < 16; l++) { s[l] = red[l] * 0.03125f; mx = fmaxf(mx, s[l]); }
#pragma unroll
        for (int l = 0; l < 16; l++) { s[l] = expf(s[l] - mx); sum += s[l]; }
        float inv = 1.f / sum;
#pragma unroll
        for (int l = 0; l < 16; l++) w_sh[l] = s[l] * inv;
    }
    __syncthreads();
    float w[16];
#pragma unroll
    for (int l = 0; l < 16; l++) w[l] = w_sh[l];
#pragma unroll
    for (int k = 0; k < 4; k++) {
        int hh = tid + k * 256;
        float acc = 0.f;
#pragma unroll
        for (int q = 0; q < 4; q++) {
            acc += w[4 * q + 0] * rows[k][q].x + w[4 * q + 1] * rows[k][q].y
                 + w[4 * q + 2] * rows[k][q].z + w[4 * q + 3] * rows[k][q].w;
        }
        bf16 hi, lo; bsplit(acc, hi, lo);
        A2h[(size_t)n * K2 + H_DIM + hh] = hi;
        A2l[(size_t)n * K2 + H_DIM + hh] = lo;
    }
}

__global__ void prep_kernel(const float* __restrict__ Af, float* c0,
                            bf16* A2h, bf16* A2l) {
    __shared__ float h_sh[H_DIM];
    __shared__ float red[16];
    __shared__ float w_sh[16];
    const int n = blockIdx.x, tid = threadIdx.x;
    if (tid < 16) red[tid] = 0.f;
#pragma unroll
    for (int k = 0; k < 4; k++) {
        int hh = tid + k * 256;
        const float4* src = (const float4*)(Af + ((size_t)n * H_DIM + hh) * 16);
        float s = 0.f;
#pragma unroll
        for (int q = 0; q < 4; q++) { float4 r = src[q]; s += r.x + r.y + r.z + r.w; }
        float m = s * 0.0625f;
        c0[(size_t)n * H_DIM + hh] = m;
        h_sh[hh] = m;
        bf16 hi, lo; bsplit(m, hi, lo);
        A2h[(size_t)n * K2 + hh] = hi; A2l[(size_t)n * K2 + hh] = lo;
    }
    __syncthreads();
    attn_body(Af, h_sh, red, w_sh, A2h, A2l, n, tid);
}

__global__ void splitx_kernel(const float* __restrict__ x, bf16* xh, bf16* xl) {
    int i = blockIdx.x * blockDim.x + threadIdx.x;
    bf16 hi, lo; bsplit(x[i], hi, lo);
    xh[i] = hi; xl[i] = lo;
}
__global__ void twx_kernel(const float* __restrict__ Wx, bf16* th, bf16* tl) {
    int i = blockIdx.x * blockDim.x + threadIdx.x;
    int n = i >> 9, k = i & 511;
    bf16 hi, lo; bsplit(Wx[(size_t)k * G4 + n], hi, lo);
    th[i] = hi; tl[i] = lo;
}
__global__ void twc_kernel(const float* __restrict__ Wh, const float* __restrict__ Wa,
                           bf16* th, bf16* tl) {
    int i = blockIdx.x * blockDim.x + threadIdx.x;
    int n = i >> 11, k = i & 2047;
    float v = (k < H_DIM) ? Wh[(size_t)k * G4 + n] : Wa[(size_t)(k - H_DIM) * G4 + n];
    bf16 hi, lo; bsplit(v, hi, lo);
    th[i] = hi; tl[i] = lo;
}

__global__ void lstm_attn_kernel(const float* __restrict__ hw, const float* __restrict__ XW,
                                 const float* __restrict__ Af,
                                 float* __restrict__ c,
                                 bf16* A2h, bf16* A2l, float* __restrict__ out, int t) {
    __shared__ float h_sh[H_DIM];
    __shared__ float red[16];
    __shared__ float w_sh[16];
    const int n = blockIdx.x, tid = threadIdx.x;
    if (tid < 16) red[tid] = 0.f;
    const float* hr = hw + (size_t)n * G4;
    const float* xr = XW + ((size_t)n * T_STEPS + t) * G4;
#pragma unroll
    for (int k = 0; k < 4; k++) {
        int j = tid + k * 256;
        size_t idx = (size_t)n * H_DIM + j;
        float ai = hr[j] + xr[j];
        float af = hr[H_DIM + j] + xr[H_DIM + j];
        float ao = hr[2 * H_DIM + j] + xr[2 * H_DIM + j];
        float ag = hr[3 * H_DIM + j] + xr[3 * H_DIM + j];
        float i_ = 1.f / (1.f + expf(-ai));
        float f_ = 1.f / (1.f + expf(-af));
        float o_ = 1.f / (1.f + expf(-ao));
        float g_ = tanhf(ag);
        float cn = f_ * c[idx] + i_ * g_;
        float hn = o_ * tanhf(cn);
        c[idx] = cn;
        h_sh[j] = hn;
        out[((size_t)n * T_STEPS + t) * H_DIM + j] = hn;
        bf16 hi, lo; bsplit(hn, hi, lo);
        A2h[(size_t)n * K2 + j] = hi;
        A2l[(size_t)n * K2 + j] = lo;
    }
    __syncthreads();
    attn_body(Af, h_sh, red, w_sh, A2h, A2l, n, tid);
}

extern "C" void kernel_launch(void* const* d_in, const int* in_sizes, int n_in,
                              void* d_out, int out_size) {
    const float* x     = (const float*)d_in[0];
    const float* Af    = (const float*)d_in[1];
    const float* Wx    = (const float*)d_in[2];
    const float* Wh    = (const float*)d_in[3];
    const float* Wattn = (const float*)d_in[4];
    const float* b     = (const float*)d_in[5];
    float* out = (float*)d_out;

    float *XW, *c, *hw;
    bf16 *xh, *xl, *Wxh, *Wxl, *Wch, *Wcl, *A2h, *A2l;
    cudaGetSymbolAddress((void**)&XW, g_XW);
    cudaGetSymbolAddress((void**)&xh, g_xh);   cudaGetSymbolAddress((void**)&xl, g_xl);
    cudaGetSymbolAddress((void**)&Wxh, g_Wxh); cudaGetSymbolAddress((void**)&Wxl, g_Wxl);
    cudaGetSymbolAddress((void**)&Wch, g_Wch); cudaGetSymbolAddress((void**)&Wcl, g_Wcl);
    cudaGetSymbolAddress((void**)&A2h, g_A2h); cudaGetSymbolAddress((void**)&A2l, g_A2l);
    cudaGetSymbolAddress((void**)&c, g_c);     cudaGetSymbolAddress((void**)&hw, g_hw);

    cudaFuncSetAttribute(gemm_kernel, cudaFuncAttributeMaxDynamicSharedMemorySize, GSMEM);
    cudaFuncSetAttribute(gemm_step_kernel, cudaFuncAttributeMaxDynamicSharedMemorySize, GSMEM2);

    prep_kernel<<<N_BATCH, 256>>>(Af, c, A2h, A2l);
    splitx_kernel<<<(N_BATCH * T_STEPS * D_IN) / 256, 256>>>(x, xh, xl);
    twx_kernel<<<(G4 * D_IN) / 256, 256>>>(Wx, Wxh, Wxl);
    twc_kernel<<<(G4 * K2) / 256, 256>>>(Wh, Wattn, Wch, Wcl);

    // XW = x @ Wx + b for all t  (M = N*T = 65536)
    {
        dim3 grid(G4 / 128, (N_BATCH * T_STEPS) / 128);
        gemm_kernel<<<grid, 256, GSMEM>>>(xh, xl, D_IN, Wxh, Wxl, D_IN, b, XW, D_IN, G4);
    }

    dim3 gstep(G4 / 256, N_BATCH / 128);   // 16 x 8 = 128 CTAs = one wave
    for (int t = 0; t < T_STEPS; t++) {
        gemm_step_kernel<<<gstep, 512, GSMEM2>>>(A2h, A2l, Wch, Wcl, hw);
        lstm_attn_kernel<<<N_BATCH, 256>>>(hw, XW, Af, c, A2h, A2l, out, t);
    }
}

// round 8
// speedup vs baseline: 1.4577x; 1.2920x over previous
#include <cuda_runtime.h>
#include <cuda_fp16.h>
#include <cstdint>

#define N_BATCH 1024
#define T_STEPS 64
#define D_IN    512
#define H_DIM   1024
#define G4      4096
#define K2      2048

__device__ float  g_XW [(size_t)N_BATCH * T_STEPS * G4];
__device__ __half g_x  [(size_t)N_BATCH * T_STEPS * D_IN];   // x single fp16
__device__ __half g_Wxh[(size_t)G4 * D_IN];                  // Wx^T hi
__device__ __half g_Wxl[(size_t)G4 * D_IN];                  // Wx^T lo
__device__ __half g_Wch[(size_t)G4 * K2];                    // [Wh;Wattn]^T hi
__device__ __half g_Wcl[(size_t)G4 * K2];                    // [Wh;Wattn]^T lo
__device__ __half g_A2 [(size_t)N_BATCH * K2];               // [h | attn] single fp16
__device__ float  g_c  [(size_t)N_BATCH * H_DIM];
__device__ float  g_hw [(size_t)N_BATCH * G4];

// ---- helpers ----
__device__ __forceinline__ uint32_t s2u(const void* p) {
    uint32_t a;
    asm("{.reg .u64 t; cvta.to.shared.u64 t, %1; cvt.u32.u64 %0, t;}" : "=r"(a) : "l"(p));
    return a;
}
#define SW128(o) ((o) ^ (((o) >> 3) & 0x70))
__device__ __forceinline__ void cpa(uint32_t s, const void* g) {
    asm volatile("cp.async.cg.shared.global [%0], [%1], 16;" :: "r"(s), "l"(g));
}
#define CP_COMMIT() asm volatile("cp.async.commit_group;" ::: "memory")
#define CP_WAIT1()  asm volatile("cp.async.wait_group 1;" ::: "memory")

__device__ __forceinline__ void mma16816(float* c, const uint32_t* a, const uint32_t* b) {
    asm volatile("mma.sync.aligned.m16n8k16.row.col.f32.f16.f16.f32 "
        "{%0,%1,%2,%3}, {%4,%5,%6,%7}, {%8,%9}, {%0,%1,%2,%3};"
        : "+f"(c[0]), "+f"(c[1]), "+f"(c[2]), "+f"(c[3])
        : "r"(a[0]), "r"(a[1]), "r"(a[2]), "r"(a[3]), "r"(b[0]), "r"(b[1]));
}
__device__ __forceinline__ void ldsm4(uint32_t* r, uint32_t a) {
    asm volatile("ldmatrix.sync.aligned.m8n8.x4.shared.b16 {%0,%1,%2,%3}, [%4];"
        : "=r"(r[0]), "=r"(r[1]), "=r"(r[2]), "=r"(r[3]) : "r"(a));
}
__device__ __forceinline__ void ldsm2(uint32_t* r, uint32_t a) {
    asm volatile("ldmatrix.sync.aligned.m8n8.x2.shared.b16 {%0,%1}, [%2];"
        : "=r"(r[0]), "=r"(r[1]) : "r"(a));
}
__device__ __forceinline__ void hsplit(float x, __half& hi, __half& lo) {
    hi = __float2half_rn(x);
    lo = __float2half_rn(x - __half2float(hi));
}

// ===== XW GEMM: 128x128, BK=64, 3-stage; A single fp16, W split (2 MMAs) ====
// stage: A 16KB | Bh 16KB | Bl 16KB = 48KB; 3 stages = 144KB
#define GSMEM (3 * 49152)
__global__ void __launch_bounds__(256, 1)
gemm_xw_kernel(const __half* __restrict__ A, int lda,
               const __half* __restrict__ Bh, const __half* __restrict__ Bl, int ldb,
               const float* __restrict__ bias, float* __restrict__ C, int K, int Nc) {
    extern __shared__ char smx[];
    const uint32_t sb = s2u(smx);
    const int tid = threadIdx.x, wid = tid >> 5, lane = tid & 31;
    const int bm = blockIdx.y * 128, bn = blockIdx.x * 128;
    const int wm = (wid >> 2) * 64, wn = (wid & 3) * 32;

    uint32_t so[4];
#pragma unroll
    for (int i = 0; i < 4; i++)
        so[i] = SW128((uint32_t)(((tid >> 3) + i * 32) * 128 + (tid & 7) * 16));

    const int KT = K / 64;
    float acc[4][4][4];
#pragma unroll
    for (int mt = 0; mt < 4; mt++)
#pragma unroll
        for (int nt = 0; nt < 4; nt++)
#pragma unroll
            for (int v = 0; v < 4; v++) acc[mt][nt][v] = 0.f;

    auto load_stage = [&](int kt, int st) {
        if (kt < KT) {
            uint32_t s0 = sb + st * 49152;
#pragma unroll
            for (int i = 0; i < 4; i++) {
                int r = (tid >> 3) + i * 32;
                size_t ga = (size_t)(bm + r) * lda + kt * 64 + (tid & 7) * 8;
                size_t gb = (size_t)(bn + r) * ldb + kt * 64 + (tid & 7) * 8;
                cpa(s0 + so[i],         A + ga);
                cpa(s0 + 16384 + so[i], Bh + gb);
                cpa(s0 + 32768 + so[i], Bl + gb);
            }
        }
        CP_COMMIT();
    };

    load_stage(0, 0);
    load_stage(1, 1);

    const int arow  = wm + (lane & 7) + ((lane >> 3) & 1) * 8;
    const int acolb = ((lane >> 4) & 1) * 16;
    const int brow  = wn + (lane & 7);
    const int bcolb = ((lane >> 3) & 1) * 16;

    for (int kt = 0; kt < KT; kt++) {
        CP_WAIT1();
        __syncthreads();
        load_stage(kt + 2, (kt + 2) % 3);

        uint32_t s0 = sb + (kt % 3) * 49152;
#pragma unroll
        for (int ks = 0; ks < 4; ks++) {
            uint32_t ah[4][4], bh[4][2], bl[4][2];
#pragma unroll
            for (int mt = 0; mt < 4; mt++) {
                uint32_t off = SW128((uint32_t)((arow + mt * 16) * 128 + ks * 32 + acolb));
                ldsm4(ah[mt], s0 + off);
            }
#pragma unroll
            for (int nt = 0; nt < 4; nt++) {
                uint32_t off = SW128((uint32_t)((brow + nt * 8) * 128 + ks * 32 + bcolb));
                ldsm2(bh[nt], s0 + 16384 + off);
                ldsm2(bl[nt], s0 + 32768 + off);
            }
#pragma unroll
            for (int mt = 0; mt < 4; mt++)
#pragma unroll
                for (int nt = 0; nt < 4; nt++) {
                    mma16816(acc[mt][nt], ah[mt], bh[nt]);
                    mma16816(acc[mt][nt], ah[mt], bl[nt]);
                }
        }
        __syncthreads();
    }

    const int q = lane >> 2, i2 = (lane & 3) * 2;
#pragma unroll
    for (int mt = 0; mt < 4; mt++) {
        int row0 = bm + wm + mt * 16 + q;
#pragma unroll
        for (int nt = 0; nt < 4; nt++) {
            int col = bn + wn + nt * 8 + i2;
            float2 v0 = make_float2(acc[mt][nt][0], acc[mt][nt][1]);
            float2 v1 = make_float2(acc[mt][nt][2], acc[mt][nt][3]);
            float2 bb = *(const float2*)(bias + col);
            v0.x += bb.x; v0.y += bb.y; v1.x += bb.x; v1.y += bb.y;
            *(float2*)(C + (size_t)row0 * Nc + col)       = v0;
            *(float2*)(C + (size_t)(row0 + 8) * Nc + col) = v1;
        }
    }
}

// ===== STEP GEMM: 128x256, 512 thr (2Mx8N), BK=64, 2-stage; 2 MMAs ==========
// stage: A 16KB | Bh 32KB | Bl 32KB = 80KB; 2 stages = 160KB. grid 16x8 = 128.
#define GSMEM2 (2 * 81920)
__global__ void __launch_bounds__(512, 1)
gemm_step_kernel(const __half* __restrict__ A,
                 const __half* __restrict__ Bh, const __half* __restrict__ Bl,
                 float* __restrict__ C) {
    extern __shared__ char smx[];
    const uint32_t sb = s2u(smx);
    const int tid = threadIdx.x, wid = tid >> 5, lane = tid & 31;
    const int bm = blockIdx.y * 128, bn = blockIdx.x * 256;
    const int wm = (wid >> 3) * 64, wn = (wid & 7) * 32;
    const int KT = K2 / 64;   // 32

    uint32_t soA[2], soB[4];
#pragma unroll
    for (int i = 0; i < 2; i++) {
        int u = tid + i * 512;
        soA[i] = SW128((uint32_t)((u >> 3) * 128 + (u & 7) * 16));
    }
#pragma unroll
    for (int i = 0; i < 4; i++) {
        int u = tid + i * 512;
        soB[i] = SW128((uint32_t)((u >> 3) * 128 + (u & 7) * 16));
    }

    float acc[4][4][4];
#pragma unroll
    for (int mt = 0; mt < 4; mt++)
#pragma unroll
        for (int nt = 0; nt < 4; nt++)
#pragma unroll
            for (int v = 0; v < 4; v++) acc[mt][nt][v] = 0.f;

    auto load_stage = [&](int kt, int st) {
        if (kt < KT) {
            uint32_t s0 = sb + st * 81920;
#pragma unroll
            for (int i = 0; i < 2; i++) {
                int u = tid + i * 512;
                size_t ga = (size_t)(bm + (u >> 3)) * K2 + kt * 64 + (u & 7) * 8;
                cpa(s0 + soA[i], A + ga);
            }
#pragma unroll
            for (int i = 0; i < 4; i++) {
                int u = tid + i * 512;
                size_t gb = (size_t)(bn + (u >> 3)) * K2 + kt * 64 + (u & 7) * 8;
                cpa(s0 + 16384 + soB[i], Bh + gb);
                cpa(s0 + 49152 + soB[i], Bl + gb);
            }
        }
        CP_COMMIT();
    };

    load_stage(0, 0);
    load_stage(1, 1);

    const int arow  = wm + (lane & 7) + ((lane >> 3) & 1) * 8;
    const int acolb = ((lane >> 4) & 1) * 16;
    const int brow  = wn + (lane & 7);
    const int bcolb = ((lane >> 3) & 1) * 16;

    for (int kt = 0; kt < KT; kt++) {
        CP_WAIT1();
        __syncthreads();
        uint32_t s0 = sb + (kt & 1) * 81920;
#pragma unroll
        for (int ks = 0; ks < 4; ks++) {
            uint32_t ah[4][4], bh[4][2], bl[4][2];
#pragma unroll
            for (int mt = 0; mt < 4; mt++) {
                uint32_t off = SW128((uint32_t)((arow + mt * 16) * 128 + ks * 32 + acolb));
                ldsm4(ah[mt], s0 + off);
            }
#pragma unroll
            for (int nt = 0; nt < 4; nt++) {
                uint32_t off = SW128((uint32_t)((brow + nt * 8) * 128 + ks * 32 + bcolb));
                ldsm2(bh[nt], s0 + 16384 + off);
                ldsm2(bl[nt], s0 + 49152 + off);
            }
#pragma unroll
            for (int mt = 0; mt < 4; mt++)
#pragma unroll
                for (int nt = 0; nt < 4; nt++) {
                    mma16816(acc[mt][nt], ah[mt], bh[nt]);
                    mma16816(acc[mt][nt], ah[mt], bl[nt]);
                }
        }
        __syncthreads();
        load_stage(kt + 2, kt & 1);
    }

    const int q = lane >> 2, i2 = (lane & 3) * 2;
#pragma unroll
    for (int mt = 0; mt < 4; mt++) {
        int row0 = bm + wm + mt * 16 + q;
#pragma unroll
        for (int nt = 0; nt < 4; nt++) {
            int col = bn + wn + nt * 8 + i2;
            *(float2*)(C + (size_t)row0 * G4 + col) =
                make_float2(acc[mt][nt][0], acc[mt][nt][1]);
            *(float2*)(C + (size_t)(row0 + 8) * G4 + col) =
                make_float2(acc[mt][nt][2], acc[mt][nt][3]);
        }
    }
}

// ---- shared attention body -----------------------------------------------
__device__ __forceinline__ void attn_body(const float* __restrict__ Af,
                                          const float* h_sh, float* red, float* w_sh,
                                          __half* A2, int n, int tid) {
    float part[16];
#pragma unroll
    for (int l = 0; l < 16; l++) part[l] = 0.f;
    const float* Ab = Af + (size_t)n * (H_DIM * 16);
    float4 rows[4][4];
#pragma unroll
    for (int k = 0; k < 4; k++) {
        int hh = tid + k * 256;
        float hv = h_sh[hh];
        const float4* row = (const float4*)(Ab + (size_t)hh * 16);
#pragma unroll
        for (int q = 0; q < 4; q++) rows[k][q] = row[q];
#pragma unroll
        for (int q = 0; q < 4; q++) {
            part[4 * q + 0] += hv * rows[k][q].x;
            part[4 * q + 1] += hv * rows[k][q].y;
            part[4 * q + 2] += hv * rows[k][q].z;
            part[4 * q + 3] += hv * rows[k][q].w;
        }
    }
#pragma unroll
    for (int l = 0; l < 16; l++) {
        float v = part[l];
        v += __shfl_down_sync(~0u, v, 16);
        v += __shfl_down_sync(~0u, v, 8);
        v += __shfl_down_sync(~0u, v, 4);
        v += __shfl_down_sync(~0u, v, 2);
        v += __shfl_down_sync(~0u, v, 1);
        if ((tid & 31) == 0) atomicAdd(&red[l], v);
    }
    __syncthreads();
    if (tid == 0) {
        float s[16], mx = -1e30f, sum = 0.f;
#pragma unroll
        for (int l = 0; l < 16; l++) { s[l] = red[l] * 0.03125f; mx = fmaxf(mx, s[l]); }
#pragma unroll
        for (int l = 0; l < 16; l++) { s[l] = expf(s[l] - mx); sum += s[l]; }
        float inv = 1.f / sum;
#pragma unroll
        for (int l = 0; l < 16; l++) w_sh[l] = s[l] * inv;
    }
    __syncthreads();
    float w[16];
#pragma unroll
    for (int l = 0; l < 16; l++) w[l] = w_sh[l];
#pragma unroll
    for (int k = 0; k < 4; k++) {
        int hh = tid + k * 256;
        float acc = 0.f;
#pragma unroll
        for (int q = 0; q < 4; q++) {
            acc += w[4 * q + 0] * rows[k][q].x + w[4 * q + 1] * rows[k][q].y
                 + w[4 * q + 2] * rows[k][q].z + w[4 * q + 3] * rows[k][q].w;
        }
        A2[(size_t)n * K2 + H_DIM + hh] = __float2half_rn(acc);
    }
}

__global__ void prep_kernel(const float* __restrict__ Af, float* c0, __half* A2) {
    __shared__ float h_sh[H_DIM];
    __shared__ float red[16];
    __shared__ float w_sh[16];
    const int n = blockIdx.x, tid = threadIdx.x;
    if (tid < 16) red[tid] = 0.f;
#pragma unroll
    for (int k = 0; k < 4; k++) {
        int hh = tid + k * 256;
        const float4* src = (const float4*)(Af + ((size_t)n * H_DIM + hh) * 16);
        float s = 0.f;
#pragma unroll
        for (int q = 0; q < 4; q++) { float4 r = src[q]; s += r.x + r.y + r.z + r.w; }
        float m = s * 0.0625f;
        c0[(size_t)n * H_DIM + hh] = m;
        h_sh[hh] = m;
        A2[(size_t)n * K2 + hh] = __float2half_rn(m);
    }
    __syncthreads();
    attn_body(Af, h_sh, red, w_sh, A2, n, tid);
}

__global__ void splitx_kernel(const float* __restrict__ x, __half* xo) {
    int i = blockIdx.x * blockDim.x + threadIdx.x;
    xo[i] = __float2half_rn(x[i]);
}
__global__ void twx_kernel(const float* __restrict__ Wx, __half* th, __half* tl) {
    int i = blockIdx.x * blockDim.x + threadIdx.x;
    int n = i >> 9, k = i & 511;
    __half hi, lo; hsplit(Wx[(size_t)k * G4 + n], hi, lo);
    th[i] = hi; tl[i] = lo;
}
__global__ void twc_kernel(const float* __restrict__ Wh, const float* __restrict__ Wa,
                           __half* th, __half* tl) {
    int i = blockIdx.x * blockDim.x + threadIdx.x;
    int n = i >> 11, k = i & 2047;
    float v = (k < H_DIM) ? Wh[(size_t)k * G4 + n] : Wa[(size_t)(k - H_DIM) * G4 + n];
    __half hi, lo; hsplit(v, hi, lo);
    th[i] = hi; tl[i] = lo;
}

__global__ void lstm_attn_kernel(const float* __restrict__ hw, const float* __restrict__ XW,
                                 const float* __restrict__ Af,
                                 float* __restrict__ c,
                                 __half* A2, float* __restrict__ out, int t) {
    __shared__ float h_sh[H_DIM];
    __shared__ float red[16];
    __shared__ float w_sh[16];
    const int n = blockIdx.x, tid = threadIdx.x;
    if (tid < 16) red[tid] = 0.f;
    const float* hr = hw + (size_t)n * G4;
    const float* xr = XW + ((size_t)n * T_STEPS + t) * G4;
#pragma unroll
    for (int k = 0; k < 4; k++) {
        int j = tid + k * 256;
        size_t idx = (size_t)n * H_DIM + j;
        float ai = hr[j] + xr[j];
        float af = hr[H_DIM + j] + xr[H_DIM + j];
        float ao = hr[2 * H_DIM + j] + xr[2 * H_DIM + j];
        float ag = hr[3 * H_DIM + j] + xr[3 * H_DIM + j];
        float i_ = 1.f / (1.f + expf(-ai));
        float f_ = 1.f / (1.f + expf(-af));
        float o_ = 1.f / (1.f + expf(-ao));
        float g_ = tanhf(ag);
        float cn = f_ * c[idx] + i_ * g_;
        float hn = o_ * tanhf(cn);
        c[idx] = cn;
        h_sh[j] = hn;
        out[((size_t)n * T_STEPS + t) * H_DIM + j] = hn;
        A2[(size_t)n * K2 + j] = __float2half_rn(hn);
    }
    __syncthreads();
    attn_body(Af, h_sh, red, w_sh, A2, n, tid);
}

extern "C" void kernel_launch(void* const* d_in, const int* in_sizes, int n_in,
                              void* d_out, int out_size) {
    const float* x     = (const float*)d_in[0];
    const float* Af    = (const float*)d_in[1];
    const float* Wx    = (const float*)d_in[2];
    const float* Wh    = (const float*)d_in[3];
    const float* Wattn = (const float*)d_in[4];
    const float* b     = (const float*)d_in[5];
    float* out = (float*)d_out;

    float *XW, *c, *hw;
    __half *xv, *Wxh, *Wxl, *Wch, *Wcl, *A2;
    cudaGetSymbolAddress((void**)&XW, g_XW);
    cudaGetSymbolAddress((void**)&xv, g_x);
    cudaGetSymbolAddress((void**)&Wxh, g_Wxh); cudaGetSymbolAddress((void**)&Wxl, g_Wxl);
    cudaGetSymbolAddress((void**)&Wch, g_Wch); cudaGetSymbolAddress((void**)&Wcl, g_Wcl);
    cudaGetSymbolAddress((void**)&A2, g_A2);
    cudaGetSymbolAddress((void**)&c, g_c);     cudaGetSymbolAddress((void**)&hw, g_hw);

    cudaFuncSetAttribute(gemm_xw_kernel, cudaFuncAttributeMaxDynamicSharedMemorySize, GSMEM);
    cudaFuncSetAttribute(gemm_step_kernel, cudaFuncAttributeMaxDynamicSharedMemorySize, GSMEM2);

    prep_kernel<<<N_BATCH, 256>>>(Af, c, A2);
    splitx_kernel<<<(N_BATCH * T_STEPS * D_IN) / 256, 256>>>(x, xv);
    twx_kernel<<<(G4 * D_IN) / 256, 256>>>(Wx, Wxh, Wxl);
    twc_kernel<<<(G4 * K2) / 256, 256>>>(Wh, Wattn, Wch, Wcl);

    // XW = x @ Wx + b for all t  (M = N*T = 65536)
    {
        dim3 grid(G4 / 128, (N_BATCH * T_STEPS) / 128);
        gemm_xw_kernel<<<grid, 256, GSMEM>>>(xv, D_IN, Wxh, Wxl, D_IN, b, XW, D_IN, G4);
    }

    dim3 gstep(G4 / 256, N_BATCH / 128);   // 16 x 8 = 128 CTAs = one wave
    for (int t = 0; t < T_STEPS; t++) {
        gemm_step_kernel<<<gstep, 512, GSMEM2>>>(A2, Wch, Wcl, hw);
        lstm_attn_kernel<<<N_BATCH, 256>>>(hw, XW, Af, c, A2, out, t);
    }
}